// round 3
// baseline (speedup 1.0000x reference)
#include <cuda_runtime.h>
#include <math.h>

// Problem constants
#define BATCH   16384
#define IDIM    512
#define HDIM    512
#define FOURH   2048
#define LN_EPS  1e-5f

// Scratch: pre-activation GEMM outputs [B, 4H] each (no bias yet).
__device__ float g_wi[(size_t)BATCH * FOURH]; // x  @ w_ih
__device__ float g_wh[(size_t)BATCH * FOURH]; // h0 @ w_hh

// ---------------------------------------------------------------------------
// SGEMM: C[M,N] = A[M,K] * B[K,N], row-major, fp32.
// 128x128 tile, BK=8, 256 threads, 8x8 per thread, double-buffered smem.
// ---------------------------------------------------------------------------
#define BM 128
#define BN 128
#define BK 8
#define TM 8
#define TN 8

__global__ __launch_bounds__(256, 2)
void sgemm_kernel(const float* __restrict__ A,
                  const float* __restrict__ Bw,
                  float* __restrict__ C,
                  int M, int N, int K)
{
    __shared__ float As[2][BK][BM];   // transposed: [k][row]
    __shared__ float Bs[2][BK][BN];

    const int tid  = threadIdx.x;
    const int brow = blockIdx.y * BM;
    const int bcol = blockIdx.x * BN;

    // Global-load mapping (float4 per thread per tile per operand)
    const int a_row = tid >> 1;            // 0..127
    const int a_col = (tid & 1) * 4;       // 0 or 4
    const int b_row = tid >> 5;            // 0..7
    const int b_col = (tid & 31) * 4;      // 0..124

    // Compute mapping: 16x16 thread grid, 8x8 microtile
    const int tx = tid & 15;
    const int ty = tid >> 4;

    float acc[TM][TN];
#pragma unroll
    for (int i = 0; i < TM; ++i)
#pragma unroll
        for (int j = 0; j < TN; ++j) acc[i][j] = 0.0f;

    const float* Aptr = A + (size_t)(brow + a_row) * K + a_col;
    const float* Bptr = Bw + (size_t)b_row * N + bcol + b_col;

    // Preload tile 0
    float4 ta = *(const float4*)(Aptr);
    float4 tb = *(const float4*)(Bptr);
    As[0][a_col + 0][a_row] = ta.x;
    As[0][a_col + 1][a_row] = ta.y;
    As[0][a_col + 2][a_row] = ta.z;
    As[0][a_col + 3][a_row] = ta.w;
    *(float4*)&Bs[0][b_row][b_col] = tb;
    __syncthreads();

    const int NT = K / BK;
    for (int kt = 0; kt < NT; ++kt) {
        if (kt + 1 < NT) {
            ta = *(const float4*)(Aptr + (kt + 1) * BK);
            tb = *(const float4*)(Bptr + (size_t)(kt + 1) * BK * N);
        }
        const int buf = kt & 1;
#pragma unroll
        for (int kk = 0; kk < BK; ++kk) {
            float af[TM], bf[TN];
#pragma unroll
            for (int i = 0; i < TM; ++i) af[i] = As[buf][kk][ty * TM + i];
#pragma unroll
            for (int j = 0; j < TN; ++j) bf[j] = Bs[buf][kk][tx * TN + j];
#pragma unroll
            for (int i = 0; i < TM; ++i)
#pragma unroll
                for (int j = 0; j < TN; ++j)
                    acc[i][j] = fmaf(af[i], bf[j], acc[i][j]);
        }
        if (kt + 1 < NT) {
            const int nb = (kt + 1) & 1;
            As[nb][a_col + 0][a_row] = ta.x;
            As[nb][a_col + 1][a_row] = ta.y;
            As[nb][a_col + 2][a_row] = ta.z;
            As[nb][a_col + 3][a_row] = ta.w;
            *(float4*)&Bs[nb][b_row][b_col] = tb;
            __syncthreads();
        }
    }

    // Store 8x8 per thread (two float4 per row)
#pragma unroll
    for (int i = 0; i < TM; ++i) {
        const int r = brow + ty * TM + i;
        float* Crow = C + (size_t)r * N + bcol + tx * TN;
        *(float4*)(Crow)     = make_float4(acc[i][0], acc[i][1], acc[i][2], acc[i][3]);
        *(float4*)(Crow + 4) = make_float4(acc[i][4], acc[i][5], acc[i][6], acc[i][7]);
    }
}

// ---------------------------------------------------------------------------
// Fused epilogue: per batch row b (one block of 256 threads):
//   dual LayerNorm over 4H of (wh+bias_h) and (wi+bias_x), gate math,
//   LayerNorm over c1 (H), outputs h1 and c1.
// out layout: [h1 (B*H floats)] [c1 (B*H floats)]
// ---------------------------------------------------------------------------
__device__ __forceinline__ float sigmoidf_(float v) {
    return 1.0f / (1.0f + expf(-v));
}

__global__ __launch_bounds__(256)
void lstm_ln_kernel(const float* __restrict__ c0,
                    const float* __restrict__ bias_x,
                    const float* __restrict__ bias_h,
                    const float* __restrict__ g_ih,
                    const float* __restrict__ b_ih,
                    const float* __restrict__ g_hh,
                    const float* __restrict__ b_hh,
                    const float* __restrict__ g_c,
                    const float* __restrict__ b_c,
                    float* __restrict__ out)
{
    const int b = blockIdx.x;
    const int t = threadIdx.x;
    const int lane = t & 31;
    const int warp = t >> 5;

    const float* wh = g_wh + (size_t)b * FOURH;
    const float* wi = g_wi + (size_t)b * FOURH;

    __shared__ float red[32];  // per-warp partials, reused per reduction

    float vh[8], vi[8];
    float s_h = 0.f, ss_h = 0.f, s_i = 0.f, ss_i = 0.f;
#pragma unroll
    for (int r = 0; r < 8; ++r) {
        const int j = t + 256 * r;
        const float a = wh[j] + bias_h[j];
        const float c = wi[j] + bias_x[j];
        vh[r] = a; vi[r] = c;
        s_h += a; ss_h += a * a;
        s_i += c; ss_i += c * c;
    }

    // warp-level reduction of the 4 partials
#pragma unroll
    for (int off = 16; off > 0; off >>= 1) {
        s_h  += __shfl_xor_sync(0xffffffffu, s_h,  off);
        ss_h += __shfl_xor_sync(0xffffffffu, ss_h, off);
        s_i  += __shfl_xor_sync(0xffffffffu, s_i,  off);
        ss_i += __shfl_xor_sync(0xffffffffu, ss_i, off);
    }
    // cross-warp via smem (8 warps), 4 scalars packed at stride 8
    if (lane == 0) {
        red[warp]      = s_h;
        red[8 + warp]  = ss_h;
        red[16 + warp] = s_i;
        red[24 + warp] = ss_i;
    }
    __syncthreads();
    float S_h = 0.f, SS_h = 0.f, S_i = 0.f, SS_i = 0.f;
#pragma unroll
    for (int w = 0; w < 8; ++w) {
        S_h  += red[w];
        SS_h += red[8 + w];
        S_i  += red[16 + w];
        SS_i += red[24 + w];
    }

    const float inv4h   = 1.0f / (float)FOURH;
    const float mean_h  = S_h * inv4h;
    const float var_h   = SS_h * inv4h - mean_h * mean_h;
    const float rstd_h  = rsqrtf(var_h + LN_EPS);
    const float mean_i  = S_i * inv4h;
    const float var_i   = SS_i * inv4h - mean_i * mean_i;
    const float rstd_i  = rsqrtf(var_i + LN_EPS);

    float s[8];
#pragma unroll
    for (int r = 0; r < 8; ++r) {
        const int j = t + 256 * r;
        const float lh = (vh[r] - mean_h) * rstd_h * g_hh[j] + b_hh[j];
        const float li = (vi[r] - mean_i) * rstd_i * g_ih[j] + b_ih[j];
        s[r] = lh + li;
    }
    // s layout per thread: r=0,1 -> f(t, 256+t); r=2,3 -> i; r=4,5 -> o; r=6,7 -> g

    const float c0_0 = c0[(size_t)b * HDIM + t];
    const float c0_1 = c0[(size_t)b * HDIM + 256 + t];

    const float c1_0 = sigmoidf_(s[0]) * c0_0 + sigmoidf_(s[2]) * tanhf(s[6]);
    const float c1_1 = sigmoidf_(s[1]) * c0_1 + sigmoidf_(s[3]) * tanhf(s[7]);

    // LayerNorm over c1 (H=512: 2 values per thread)
    float sc  = c1_0 + c1_1;
    float ssc = c1_0 * c1_0 + c1_1 * c1_1;
#pragma unroll
    for (int off = 16; off > 0; off >>= 1) {
        sc  += __shfl_xor_sync(0xffffffffu, sc,  off);
        ssc += __shfl_xor_sync(0xffffffffu, ssc, off);
    }
    __syncthreads();   // protect red[] reuse
    if (lane == 0) {
        red[warp]     = sc;
        red[8 + warp] = ssc;
    }
    __syncthreads();
    float Sc = 0.f, SSc = 0.f;
#pragma unroll
    for (int w = 0; w < 8; ++w) { Sc += red[w]; SSc += red[8 + w]; }

    const float invh   = 1.0f / (float)HDIM;
    const float mean_c = Sc * invh;
    const float var_c  = SSc * invh - mean_c * mean_c;
    const float rstd_c = rsqrtf(var_c + LN_EPS);

    const float lc0 = (c1_0 - mean_c) * rstd_c * g_c[t]       + b_c[t];
    const float lc1 = (c1_1 - mean_c) * rstd_c * g_c[256 + t] + b_c[256 + t];

    const float h1_0 = sigmoidf_(s[4]) * tanhf(lc0);
    const float h1_1 = sigmoidf_(s[5]) * tanhf(lc1);

    // out: h1 first, then c1
    float* out_h1 = out;
    float* out_c1 = out + (size_t)BATCH * HDIM;
    out_h1[(size_t)b * HDIM + t]        = h1_0;
    out_h1[(size_t)b * HDIM + 256 + t]  = h1_1;
    out_c1[(size_t)b * HDIM + t]        = c1_0;
    out_c1[(size_t)b * HDIM + 256 + t]  = c1_1;
}

// ---------------------------------------------------------------------------
// Launch
// ---------------------------------------------------------------------------
extern "C" void kernel_launch(void* const* d_in, const int* in_sizes, int n_in,
                              void* d_out, int out_size)
{
    const float* x      = (const float*)d_in[0];
    const float* h0     = (const float*)d_in[1];
    const float* c0     = (const float*)d_in[2];
    const float* w_ih   = (const float*)d_in[3];
    const float* w_hh   = (const float*)d_in[4];
    const float* bias_x = (const float*)d_in[5];
    const float* bias_h = (const float*)d_in[6];
    const float* g_ih   = (const float*)d_in[7];
    const float* b_ih   = (const float*)d_in[8];
    const float* g_hh   = (const float*)d_in[9];
    const float* b_hh   = (const float*)d_in[10];
    const float* g_c    = (const float*)d_in[11];
    const float* b_c    = (const float*)d_in[12];
    float* out = (float*)d_out;

    float* wi_ptr = nullptr;
    float* wh_ptr = nullptr;
    cudaGetSymbolAddress((void**)&wi_ptr, g_wi);
    cudaGetSymbolAddress((void**)&wh_ptr, g_wh);

    dim3 gemm_grid(FOURH / BN, BATCH / BM);  // (16, 128)
    sgemm_kernel<<<gemm_grid, 256>>>(x,  w_ih, wi_ptr, BATCH, FOURH, IDIM);
    sgemm_kernel<<<gemm_grid, 256>>>(h0, w_hh, wh_ptr, BATCH, FOURH, HDIM);

    lstm_ln_kernel<<<BATCH, 256>>>(c0, bias_x, bias_h, g_ih, b_ih,
                                   g_hh, b_hh, g_c, b_c, out);
}

// round 8
// speedup vs baseline: 2.8868x; 2.8868x over previous
#include <cuda_runtime.h>
#include <cuda_bf16.h>
#include <cstdint>
#include <math.h>

// ---------------------------------------------------------------------------
// Problem constants
// ---------------------------------------------------------------------------
#define BATCH   16384
#define KDIM    512          // I == H == 512 (GEMM K)
#define FOURH   2048
#define LN_EPS  1e-5f

// Scratch (device globals: allocation-guard-safe)
__device__ float g_wi[(size_t)BATCH * FOURH];     // x  @ w_ih
__device__ float g_wh[(size_t)BATCH * FOURH];     // h0 @ w_hh
// hi/lo bf16 splits of activations (row-major [B, K])
__device__ __nv_bfloat16 g_x_hi[(size_t)BATCH * KDIM];
__device__ __nv_bfloat16 g_x_lo[(size_t)BATCH * KDIM];
__device__ __nv_bfloat16 g_h_hi[(size_t)BATCH * KDIM];
__device__ __nv_bfloat16 g_h_lo[(size_t)BATCH * KDIM];
// hi/lo bf16 splits of transposed weights (K-major [4H, K])
__device__ __nv_bfloat16 g_wih_hi[(size_t)FOURH * KDIM];
__device__ __nv_bfloat16 g_wih_lo[(size_t)FOURH * KDIM];
__device__ __nv_bfloat16 g_whh_hi[(size_t)FOURH * KDIM];
__device__ __nv_bfloat16 g_whh_lo[(size_t)FOURH * KDIM];

// ---------------------------------------------------------------------------
// fp32 -> (bf16 hi, bf16 lo) elementwise split, 4 elems/thread
// ---------------------------------------------------------------------------
__global__ void split_kernel(const float* __restrict__ src,
                             __nv_bfloat16* __restrict__ hi,
                             __nv_bfloat16* __restrict__ lo,
                             size_t n4)
{
    const size_t i = (size_t)blockIdx.x * blockDim.x + threadIdx.x;
    if (i >= n4) return;
    const float4 v = ((const float4*)src)[i];
    __nv_bfloat16 h0 = __float2bfloat16(v.x);
    __nv_bfloat16 h1 = __float2bfloat16(v.y);
    __nv_bfloat16 h2 = __float2bfloat16(v.z);
    __nv_bfloat16 h3 = __float2bfloat16(v.w);
    __nv_bfloat162 hh0 = {h0, h1}, hh1 = {h2, h3};
    __nv_bfloat162 ll0 = {__float2bfloat16(v.x - __bfloat162float(h0)),
                          __float2bfloat16(v.y - __bfloat162float(h1))};
    __nv_bfloat162 ll1 = {__float2bfloat16(v.z - __bfloat162float(h2)),
                          __float2bfloat16(v.w - __bfloat162float(h3))};
    ((__nv_bfloat162*)hi)[i * 2]     = hh0;
    ((__nv_bfloat162*)hi)[i * 2 + 1] = hh1;
    ((__nv_bfloat162*)lo)[i * 2]     = ll0;
    ((__nv_bfloat162*)lo)[i * 2 + 1] = ll1;
}

// ---------------------------------------------------------------------------
// Weight transpose+split: W[K, 4H] fp32 -> WT_hi/lo[4H, K] bf16
// ---------------------------------------------------------------------------
__global__ void transpose_split_kernel(const float* __restrict__ W,
                                       __nv_bfloat16* __restrict__ WT_hi,
                                       __nv_bfloat16* __restrict__ WT_lo)
{
    __shared__ float t[32][33];
    const int bx = blockIdx.x * 32;   // col in W  (n)
    const int by = blockIdx.y * 32;   // row in W  (k)
    const int tx = threadIdx.x, ty = threadIdx.y;
#pragma unroll
    for (int i = 0; i < 32; i += 8)
        t[ty + i][tx] = W[(size_t)(by + ty + i) * FOURH + bx + tx];
    __syncthreads();
#pragma unroll
    for (int i = 0; i < 32; i += 8) {
        const float v = t[tx][ty + i];
        const __nv_bfloat16 h = __float2bfloat16(v);
        const __nv_bfloat16 l = __float2bfloat16(v - __bfloat162float(h));
        WT_hi[(size_t)(bx + ty + i) * KDIM + by + tx] = h;
        WT_lo[(size_t)(bx + ty + i) * KDIM + by + tx] = l;
    }
}

// ---------------------------------------------------------------------------
// mma.sync bf16 hi/lo GEMM (sm_80-baseline PTX; runs on HMMA tensor pipe):
//   C[M,N] = A[M,K] * B[N,K]^T  fp32-accurate via Ahi*Bhi + Ahi*Blo + Alo*Bhi.
// CTA tile 128x128, BK=64 (128B rows, xor swizzle), 3-stage cp.async ring,
// 8 warps with 64x32 warp tiles of m16n8k16 fragments.
// ---------------------------------------------------------------------------
#define BM      128
#define BN      128
#define BKE     64                       // bf16 K-elems per chunk (128 B/row)
#define STAGES  3
#define NKIT    (KDIM / BKE)             // 8
#define TILE_B  (128 * 128)              // 16 KB per operand tile
#define A_HI_OFF 0
#define A_LO_OFF (TILE_B)
#define B_HI_OFF (2 * TILE_B)
#define B_LO_OFF (3 * TILE_B)
#define STAGE_BYTES (4 * TILE_B)         // 64 KB
#define SMEM_DYN (STAGES * STAGE_BYTES + 128)

__device__ __forceinline__ uint32_t cvta_smem(const void* p) {
    return (uint32_t)__cvta_generic_to_shared(p);
}
__device__ __forceinline__ void cp16(uint32_t dst, const void* src) {
    asm volatile("cp.async.cg.shared.global [%0], [%1], 16;" :: "r"(dst), "l"(src));
}
__device__ __forceinline__ void cp_commit() {
    asm volatile("cp.async.commit_group;" ::: "memory");
}
template <int N>
__device__ __forceinline__ void cp_wait() {
    asm volatile("cp.async.wait_group %0;" :: "n"(N) : "memory");
}
__device__ __forceinline__ void ldsm4(uint32_t& r0, uint32_t& r1,
                                      uint32_t& r2, uint32_t& r3, uint32_t addr) {
    asm volatile("ldmatrix.sync.aligned.m8n8.x4.shared.b16 {%0,%1,%2,%3}, [%4];"
                 : "=r"(r0), "=r"(r1), "=r"(r2), "=r"(r3) : "r"(addr));
}
__device__ __forceinline__ void mma16816(float* d, const uint32_t* a,
                                         const uint32_t* b) {
    asm volatile(
        "mma.sync.aligned.m16n8k16.row.col.f32.bf16.bf16.f32 "
        "{%0,%1,%2,%3}, {%4,%5,%6,%7}, {%8,%9}, {%0,%1,%2,%3};"
        : "+f"(d[0]), "+f"(d[1]), "+f"(d[2]), "+f"(d[3])
        : "r"(a[0]), "r"(a[1]), "r"(a[2]), "r"(a[3]), "r"(b[0]), "r"(b[1]));
}

__global__ void __launch_bounds__(256)
gemm_bf16hl_kernel(const __nv_bfloat16* __restrict__ Axhi,
                   const __nv_bfloat16* __restrict__ Axlo,
                   const __nv_bfloat16* __restrict__ Ahhi,
                   const __nv_bfloat16* __restrict__ Ahlo,
                   const __nv_bfloat16* __restrict__ Bihi,
                   const __nv_bfloat16* __restrict__ Bilo,
                   const __nv_bfloat16* __restrict__ Bhhi,
                   const __nv_bfloat16* __restrict__ Bhlo,
                   float* __restrict__ C0, float* __restrict__ C1)
{
    extern __shared__ char dsmem_raw[];

    const int tid = threadIdx.x;
    const int wid = tid >> 5;
    const int lid = tid & 31;

    const __nv_bfloat16* Ahi = blockIdx.z ? Ahhi : Axhi;
    const __nv_bfloat16* Alo = blockIdx.z ? Ahlo : Axlo;
    const __nv_bfloat16* Bhi = blockIdx.z ? Bhhi : Bihi;
    const __nv_bfloat16* Blo = blockIdx.z ? Bhlo : Bilo;
    float*               C   = blockIdx.z ? C1   : C0;

    const int brow = blockIdx.y * BM;
    const int bcol = blockIdx.x * BN;

    uint32_t sbase = cvta_smem(dsmem_raw);
    sbase = (sbase + 127u) & ~127u;

    // Warp tile: 64 (M) x 32 (N);  warp grid 2 x 4
    const int wm = (wid & 1) * 64;
    const int wn = (wid >> 1) * 32;

    // ldmatrix lane->address decode (quad q = lid/8, r = lid%8)
    const int lq = lid >> 3;
    const int lr = lid & 7;
    // A x4: matrices (m0-7,k0-7),(m8-15,k0-7),(m0-7,k8-15),(m8-15,k8-15)
    const int a_row = lr + ((lq & 1) ? 8 : 0);
    const int a_kbh = lq >> 1;               // 0 or 1 -> +16B
    // B x4 over 2 n-tiles: (n0-7,k0-7),(n0-7,k8-15),(n8-15,k0-7),(n8-15,k8-15)
    const int b_row = lr + ((lq >> 1) ? 8 : 0);
    const int b_kbh = lq & 1;

    float acc[4][4][4];
#pragma unroll
    for (int mt = 0; mt < 4; ++mt)
#pragma unroll
        for (int nt = 0; nt < 4; ++nt)
#pragma unroll
            for (int r = 0; r < 4; ++r) acc[mt][nt][r] = 0.0f;

    // Stage loader: 4 tiles of 128 rows x 128 B; 16 cp16 per thread.
    auto load_stage = [&](int s, int kc) {
        const int k0 = kc * BKE;
        const uint32_t sb = sbase + s * STAGE_BYTES;
#pragma unroll
        for (int i = 0; i < 4; ++i) {
            const int idx = tid + 256 * i;       // 0..1023
            const int row = idx >> 3, ch = idx & 7;
            const uint32_t off = (uint32_t)(row * 128 + ((ch ^ (row & 7)) * 16));
            const size_t ga = (size_t)(brow + row) * KDIM + k0 + ch * 8;
            const size_t gb = (size_t)(bcol + row) * KDIM + k0 + ch * 8;
            cp16(sb + A_HI_OFF + off, Ahi + ga);
            cp16(sb + A_LO_OFF + off, Alo + ga);
            cp16(sb + B_HI_OFF + off, Bhi + gb);
            cp16(sb + B_LO_OFF + off, Blo + gb);
        }
        cp_commit();
    };

    // Prologue: 2 stages in flight
    load_stage(0, 0);
    load_stage(1, 1);

#pragma unroll 1
    for (int kc = 0; kc < NKIT; ++kc) {
        const int s = kc % STAGES;
        if (kc + 2 < NKIT) load_stage((kc + 2) % STAGES, kc + 2);
        else               cp_commit();          // empty group: keeps wait<2> exact
        cp_wait<2>();                            // chunk kc resident
        __syncthreads();

        const uint32_t sb  = sbase + s * STAGE_BYTES;
        const uint32_t ahb = sb + A_HI_OFF;
        const uint32_t alb = sb + A_LO_OFF;
        const uint32_t bhb = sb + B_HI_OFF;
        const uint32_t blb = sb + B_LO_OFF;

#pragma unroll
        for (int ks = 0; ks < 4; ++ks) {
            uint32_t ah[4][4], al[4][4], bh[8], bl[8];
#pragma unroll
            for (int mt = 0; mt < 4; ++mt) {
                const int row = wm + mt * 16 + a_row;
                const int ch  = ks * 2 + a_kbh;
                const uint32_t off =
                    (uint32_t)(row * 128 + ((ch ^ (row & 7)) * 16));
                ldsm4(ah[mt][0], ah[mt][1], ah[mt][2], ah[mt][3], ahb + off);
                ldsm4(al[mt][0], al[mt][1], al[mt][2], al[mt][3], alb + off);
            }
#pragma unroll
            for (int np = 0; np < 2; ++np) {
                const int row = wn + np * 16 + b_row;
                const int ch  = ks * 2 + b_kbh;
                const uint32_t off =
                    (uint32_t)(row * 128 + ((ch ^ (row & 7)) * 16));
                ldsm4(bh[np*4], bh[np*4+1], bh[np*4+2], bh[np*4+3], bhb + off);
                ldsm4(bl[np*4], bl[np*4+1], bl[np*4+2], bl[np*4+3], blb + off);
            }
#pragma unroll
            for (int mt = 0; mt < 4; ++mt)
#pragma unroll
                for (int nt = 0; nt < 4; ++nt) {
                    const int bi = (nt >> 1) * 4 + (nt & 1) * 2;
                    mma16816(acc[mt][nt], ah[mt], &bh[bi]);   // Ahi*Bhi
                    mma16816(acc[mt][nt], ah[mt], &bl[bi]);   // Ahi*Blo
                    mma16816(acc[mt][nt], al[mt], &bh[bi]);   // Alo*Bhi
                }
        }
        __syncthreads();                         // stage reusable next iter
    }

    // Epilogue: fragment layout -> C.  d0,d1: row lid/4, cols (lid%4)*2,+1;
    // d2,d3: row +8.
    const int er = lid >> 2;
    const int ec = (lid & 3) * 2;
#pragma unroll
    for (int mt = 0; mt < 4; ++mt) {
#pragma unroll
        for (int nt = 0; nt < 4; ++nt) {
            const int r0 = brow + wm + mt * 16 + er;
            const int cc = bcol + wn + nt * 8 + ec;
            *(float2*)&C[(size_t)r0 * FOURH + cc] =
                make_float2(acc[mt][nt][0], acc[mt][nt][1]);
            *(float2*)&C[(size_t)(r0 + 8) * FOURH + cc] =
                make_float2(acc[mt][nt][2], acc[mt][nt][3]);
        }
    }
}

// ---------------------------------------------------------------------------
// Fused LSTM epilogue (validated at rel_err 1.2e-7 in R3):
//   dual LN over 4H, gate math, LN over c1, outputs h1 then c1.
// ---------------------------------------------------------------------------
__device__ __forceinline__ float sigmoidf_(float v) {
    return 1.0f / (1.0f + expf(-v));
}

__global__ __launch_bounds__(256)
void lstm_ln_kernel(const float* __restrict__ c0,
                    const float* __restrict__ bias_x,
                    const float* __restrict__ bias_h,
                    const float* __restrict__ g_ih,
                    const float* __restrict__ b_ih,
                    const float* __restrict__ g_hh,
                    const float* __restrict__ b_hh,
                    const float* __restrict__ g_c,
                    const float* __restrict__ b_c,
                    float* __restrict__ out)
{
    const int b = blockIdx.x;
    const int t = threadIdx.x;
    const int lane = t & 31;
    const int warp = t >> 5;

    const float* wh = g_wh + (size_t)b * FOURH;
    const float* wi = g_wi + (size_t)b * FOURH;

    __shared__ float red[32];

    float vh[8], vi[8];
    float s_h = 0.f, ss_h = 0.f, s_i = 0.f, ss_i = 0.f;
#pragma unroll
    for (int r = 0; r < 8; ++r) {
        const int j = t + 256 * r;
        const float a = wh[j] + bias_h[j];
        const float c = wi[j] + bias_x[j];
        vh[r] = a; vi[r] = c;
        s_h += a; ss_h += a * a;
        s_i += c; ss_i += c * c;
    }
#pragma unroll
    for (int off = 16; off > 0; off >>= 1) {
        s_h  += __shfl_xor_sync(0xffffffffu, s_h,  off);
        ss_h += __shfl_xor_sync(0xffffffffu, ss_h, off);
        s_i  += __shfl_xor_sync(0xffffffffu, s_i,  off);
        ss_i += __shfl_xor_sync(0xffffffffu, ss_i, off);
    }
    if (lane == 0) {
        red[warp]      = s_h;
        red[8 + warp]  = ss_h;
        red[16 + warp] = s_i;
        red[24 + warp] = ss_i;
    }
    __syncthreads();
    float S_h = 0.f, SS_h = 0.f, S_i = 0.f, SS_i = 0.f;
#pragma unroll
    for (int w = 0; w < 8; ++w) {
        S_h  += red[w];
        SS_h += red[8 + w];
        S_i  += red[16 + w];
        SS_i += red[24 + w];
    }

    const float inv4h  = 1.0f / (float)FOURH;
    const float mean_h = S_h * inv4h;
    const float var_h  = SS_h * inv4h - mean_h * mean_h;
    const float rstd_h = rsqrtf(var_h + LN_EPS);
    const float mean_i = S_i * inv4h;
    const float var_i  = SS_i * inv4h - mean_i * mean_i;
    const float rstd_i = rsqrtf(var_i + LN_EPS);

    float s[8];
#pragma unroll
    for (int r = 0; r < 8; ++r) {
        const int j = t + 256 * r;
        const float lh = (vh[r] - mean_h) * rstd_h * g_hh[j] + b_hh[j];
        const float li = (vi[r] - mean_i) * rstd_i * g_ih[j] + b_ih[j];
        s[r] = lh + li;
    }

    const int HD = FOURH / 4;
    const float c0_0 = c0[(size_t)b * HD + t];
    const float c0_1 = c0[(size_t)b * HD + 256 + t];

    const float c1_0 = sigmoidf_(s[0]) * c0_0 + sigmoidf_(s[2]) * tanhf(s[6]);
    const float c1_1 = sigmoidf_(s[1]) * c0_1 + sigmoidf_(s[3]) * tanhf(s[7]);

    float sc  = c1_0 + c1_1;
    float ssc = c1_0 * c1_0 + c1_1 * c1_1;
#pragma unroll
    for (int off = 16; off > 0; off >>= 1) {
        sc  += __shfl_xor_sync(0xffffffffu, sc,  off);
        ssc += __shfl_xor_sync(0xffffffffu, ssc, off);
    }
    __syncthreads();
    if (lane == 0) {
        red[warp]     = sc;
        red[8 + warp] = ssc;
    }
    __syncthreads();
    float Sc = 0.f, SSc = 0.f;
#pragma unroll
    for (int w = 0; w < 8; ++w) { Sc += red[w]; SSc += red[8 + w]; }

    const float invh   = 1.0f / (float)HD;
    const float mean_c = Sc * invh;
    const float var_c  = SSc * invh - mean_c * mean_c;
    const float rstd_c = rsqrtf(var_c + LN_EPS);

    const float lc0 = (c1_0 - mean_c) * rstd_c * g_c[t]       + b_c[t];
    const float lc1 = (c1_1 - mean_c) * rstd_c * g_c[256 + t] + b_c[256 + t];

    const float h1_0 = sigmoidf_(s[4]) * tanhf(lc0);
    const float h1_1 = sigmoidf_(s[5]) * tanhf(lc1);

    float* out_h1 = out;
    float* out_c1 = out + (size_t)BATCH * HD;
    out_h1[(size_t)b * HD + t]       = h1_0;
    out_h1[(size_t)b * HD + 256 + t] = h1_1;
    out_c1[(size_t)b * HD + t]       = c1_0;
    out_c1[(size_t)b * HD + 256 + t] = c1_1;
}

// ---------------------------------------------------------------------------
// Launch
// ---------------------------------------------------------------------------
extern "C" void kernel_launch(void* const* d_in, const int* in_sizes, int n_in,
                              void* d_out, int out_size)
{
    const float* x      = (const float*)d_in[0];
    const float* h0     = (const float*)d_in[1];
    const float* c0     = (const float*)d_in[2];
    const float* w_ih   = (const float*)d_in[3];
    const float* w_hh   = (const float*)d_in[4];
    const float* bias_x = (const float*)d_in[5];
    const float* bias_h = (const float*)d_in[6];
    const float* g_ih   = (const float*)d_in[7];
    const float* b_ih   = (const float*)d_in[8];
    const float* g_hh   = (const float*)d_in[9];
    const float* b_hh   = (const float*)d_in[10];
    const float* g_c    = (const float*)d_in[11];
    const float* b_c    = (const float*)d_in[12];
    float* out = (float*)d_out;

    float *wi_ptr, *wh_ptr;
    __nv_bfloat16 *xhi, *xlo, *hhi, *hlo, *wihhi, *wihlo, *whhhi, *whhlo;
    cudaGetSymbolAddress((void**)&wi_ptr, g_wi);
    cudaGetSymbolAddress((void**)&wh_ptr, g_wh);
    cudaGetSymbolAddress((void**)&xhi,   g_x_hi);
    cudaGetSymbolAddress((void**)&xlo,   g_x_lo);
    cudaGetSymbolAddress((void**)&hhi,   g_h_hi);
    cudaGetSymbolAddress((void**)&hlo,   g_h_lo);
    cudaGetSymbolAddress((void**)&wihhi, g_wih_hi);
    cudaGetSymbolAddress((void**)&wihlo, g_wih_lo);
    cudaGetSymbolAddress((void**)&whhhi, g_whh_hi);
    cudaGetSymbolAddress((void**)&whhlo, g_whh_lo);

    cudaFuncSetAttribute(gemm_bf16hl_kernel,
                         cudaFuncAttributeMaxDynamicSharedMemorySize, SMEM_DYN);

    // Activation hi/lo splits
    const size_t n4 = (size_t)BATCH * KDIM / 4;
    split_kernel<<<(unsigned)((n4 + 255) / 256), 256>>>(x,  xhi, xlo, n4);
    split_kernel<<<(unsigned)((n4 + 255) / 256), 256>>>(h0, hhi, hlo, n4);

    // Weight transpose + hi/lo split to K-major [4H, K]
    dim3 tb(32, 8);
    dim3 tg(FOURH / 32, KDIM / 32);
    transpose_split_kernel<<<tg, tb>>>(w_ih, wihhi, wihlo);
    transpose_split_kernel<<<tg, tb>>>(w_hh, whhhi, whhlo);

    // Both GEMMs in one launch: z=0 -> wi (x @ w_ih), z=1 -> wh (h0 @ w_hh)
    dim3 gg(FOURH / BN, BATCH / BM, 2);     // (16, 128, 2)
    gemm_bf16hl_kernel<<<gg, 256, SMEM_DYN>>>(xhi, xlo, hhi, hlo,
                                              wihhi, wihlo, whhhi, whhlo,
                                              wi_ptr, wh_ptr);

    lstm_ln_kernel<<<BATCH, 256>>>(c0, bias_x, bias_h, g_ih, b_ih,
                                   g_hh, b_hh, g_c, b_c, out);
}

// round 11
// speedup vs baseline: 5.7202x; 1.9815x over previous
#include <cuda_runtime.h>
#include <cuda_fp16.h>
#include <cstdint>
#include <math.h>

// ---------------------------------------------------------------------------
// Problem constants
// ---------------------------------------------------------------------------
#define BATCH   16384
#define KDIM    512          // I == H == 512 (GEMM K)
#define FOURH   2048
#define LN_EPS  1e-5f

// Scratch (device globals: allocation-guard-safe)
__device__ float g_wi[(size_t)BATCH * FOURH];     // x  @ w_ih
__device__ float g_wh[(size_t)BATCH * FOURH];     // h0 @ w_hh
// fp16 activations (row-major [B, K])
__device__ __half g_x16[(size_t)BATCH * KDIM];
__device__ __half g_h16[(size_t)BATCH * KDIM];
// fp16 transposed weights (K-major [4H, K])
__device__ __half g_wih16[(size_t)FOURH * KDIM];
__device__ __half g_whh16[(size_t)FOURH * KDIM];

// ---------------------------------------------------------------------------
// fp32 -> fp16 convert, 4 elems/thread
// ---------------------------------------------------------------------------
__global__ void cvt16_kernel(const float* __restrict__ src,
                             __half* __restrict__ dst, size_t n4)
{
    const size_t i = (size_t)blockIdx.x * blockDim.x + threadIdx.x;
    if (i >= n4) return;
    const float4 v = ((const float4*)src)[i];
    ((__half2*)dst)[i * 2]     = __floats2half2_rn(v.x, v.y);
    ((__half2*)dst)[i * 2 + 1] = __floats2half2_rn(v.z, v.w);
}

// ---------------------------------------------------------------------------
// Weight transpose+convert: W[K, 4H] fp32 -> WT[4H, K] fp16
// ---------------------------------------------------------------------------
__global__ void transpose16_kernel(const float* __restrict__ W,
                                   __half* __restrict__ WT)
{
    __shared__ float t[32][33];
    const int bx = blockIdx.x * 32;   // col in W  (n)
    const int by = blockIdx.y * 32;   // row in W  (k)
    const int tx = threadIdx.x, ty = threadIdx.y;
#pragma unroll
    for (int i = 0; i < 32; i += 8)
        t[ty + i][tx] = W[(size_t)(by + ty + i) * FOURH + bx + tx];
    __syncthreads();
#pragma unroll
    for (int i = 0; i < 32; i += 8)
        WT[(size_t)(bx + ty + i) * KDIM + by + tx] = __float2half_rn(t[tx][ty + i]);
}

// ---------------------------------------------------------------------------
// mma.sync fp16 GEMM (single-pass, f32 accumulate):
//   C[M,N] = A[M,K] * B[N,K]^T
// CTA tile 128x128, BK=64 (128B rows, xor swizzle), 3-stage cp.async ring
// (96 KB -> 2 CTAs/SM), 8 warps with 64x32 warp tiles of m16n8k16.
// ---------------------------------------------------------------------------
#define BM      128
#define BN      128
#define BKE     64                       // fp16 K-elems per chunk (128 B/row)
#define STAGES  3
#define NKIT    (KDIM / BKE)             // 8
#define TILE_B  (128 * 128)              // 16 KB per operand tile
#define A_OFF   0
#define B_OFF   (TILE_B)
#define STAGE_BYTES (2 * TILE_B)         // 32 KB
#define SMEM_DYN (STAGES * STAGE_BYTES + 1024)   // ~97 KB -> 2 CTAs/SM

__device__ __forceinline__ uint32_t cvta_smem(const void* p) {
    return (uint32_t)__cvta_generic_to_shared(p);
}
__device__ __forceinline__ void cp16(uint32_t dst, const void* src) {
    asm volatile("cp.async.cg.shared.global [%0], [%1], 16;" :: "r"(dst), "l"(src));
}
__device__ __forceinline__ void cp_commit() {
    asm volatile("cp.async.commit_group;" ::: "memory");
}
template <int N>
__device__ __forceinline__ void cp_wait() {
    asm volatile("cp.async.wait_group %0;" :: "n"(N) : "memory");
}
__device__ __forceinline__ void ldsm4(uint32_t& r0, uint32_t& r1,
                                      uint32_t& r2, uint32_t& r3, uint32_t addr) {
    asm volatile("ldmatrix.sync.aligned.m8n8.x4.shared.b16 {%0,%1,%2,%3}, [%4];"
                 : "=r"(r0), "=r"(r1), "=r"(r2), "=r"(r3) : "r"(addr));
}
__device__ __forceinline__ void mma16816(float* d, const uint32_t* a,
                                         const uint32_t* b) {
    asm volatile(
        "mma.sync.aligned.m16n8k16.row.col.f32.f16.f16.f32 "
        "{%0,%1,%2,%3}, {%4,%5,%6,%7}, {%8,%9}, {%0,%1,%2,%3};"
        : "+f"(d[0]), "+f"(d[1]), "+f"(d[2]), "+f"(d[3])
        : "r"(a[0]), "r"(a[1]), "r"(a[2]), "r"(a[3]), "r"(b[0]), "r"(b[1]));
}

__global__ void __launch_bounds__(256, 2)
gemm_f16_kernel(const __half* __restrict__ A0, const __half* __restrict__ A1,
                const __half* __restrict__ B0, const __half* __restrict__ B1,
                float* __restrict__ C0, float* __restrict__ C1)
{
    extern __shared__ char dsmem_raw[];

    const int tid = threadIdx.x;
    const int wid = tid >> 5;
    const int lid = tid & 31;

    const __half* A = blockIdx.z ? A1 : A0;
    const __half* B = blockIdx.z ? B1 : B0;
    float*        C = blockIdx.z ? C1 : C0;

    const int brow = blockIdx.y * BM;
    const int bcol = blockIdx.x * BN;

    uint32_t sbase = cvta_smem(dsmem_raw);
    sbase = (sbase + 127u) & ~127u;

    // Warp tile: 64 (M) x 32 (N);  warp grid 2 x 4
    const int wm = (wid & 1) * 64;
    const int wn = (wid >> 1) * 32;

    // ldmatrix lane->address decode (quad q = lid/8, r = lid%8)
    const int lq = lid >> 3;
    const int lr = lid & 7;
    // A x4: matrices (m0-7,k0-7),(m8-15,k0-7),(m0-7,k8-15),(m8-15,k8-15)
    const int a_row = lr + ((lq & 1) ? 8 : 0);
    const int a_kbh = lq >> 1;               // 0 or 1 -> +16B
    // B x4 over 2 n-tiles: (n0-7,k0-7),(n0-7,k8-15),(n8-15,k0-7),(n8-15,k8-15)
    const int b_row = lr + ((lq >> 1) ? 8 : 0);
    const int b_kbh = lq & 1;

    float acc[4][4][4];
#pragma unroll
    for (int mt = 0; mt < 4; ++mt)
#pragma unroll
        for (int nt = 0; nt < 4; ++nt)
#pragma unroll
            for (int r = 0; r < 4; ++r) acc[mt][nt][r] = 0.0f;

    // Stage loader: 2 tiles of 128 rows x 128 B; 8 cp16 per thread.
    auto load_stage = [&](int s, int kc) {
        const int k0 = kc * BKE;
        const uint32_t sb = sbase + s * STAGE_BYTES;
#pragma unroll
        for (int i = 0; i < 4; ++i) {
            const int idx = tid + 256 * i;       // 0..1023
            const int row = idx >> 3, ch = idx & 7;
            const uint32_t off = (uint32_t)(row * 128 + ((ch ^ (row & 7)) * 16));
            const size_t ga = (size_t)(brow + row) * KDIM + k0 + ch * 8;
            const size_t gb = (size_t)(bcol + row) * KDIM + k0 + ch * 8;
            cp16(sb + A_OFF + off, A + ga);
            cp16(sb + B_OFF + off, B + gb);
        }
        cp_commit();
    };

    // Prologue: 2 stages in flight
    load_stage(0, 0);
    load_stage(1, 1);

#pragma unroll 1
    for (int kc = 0; kc < NKIT; ++kc) {
        const int s = kc % STAGES;
        if (kc + 2 < NKIT) load_stage((kc + 2) % STAGES, kc + 2);
        else               cp_commit();          // empty group: keeps wait<2> exact
        cp_wait<2>();                            // chunk kc resident
        __syncthreads();

        const uint32_t ab = sbase + s * STAGE_BYTES + A_OFF;
        const uint32_t bb = sbase + s * STAGE_BYTES + B_OFF;

#pragma unroll
        for (int ks = 0; ks < 4; ++ks) {
            uint32_t a[4][4], b[8];
#pragma unroll
            for (int mt = 0; mt < 4; ++mt) {
                const int row = wm + mt * 16 + a_row;
                const int ch  = ks * 2 + a_kbh;
                const uint32_t off =
                    (uint32_t)(row * 128 + ((ch ^ (row & 7)) * 16));
                ldsm4(a[mt][0], a[mt][1], a[mt][2], a[mt][3], ab + off);
            }
#pragma unroll
            for (int np = 0; np < 2; ++np) {
                const int row = wn + np * 16 + b_row;
                const int ch  = ks * 2 + b_kbh;
                const uint32_t off =
                    (uint32_t)(row * 128 + ((ch ^ (row & 7)) * 16));
                ldsm4(b[np*4], b[np*4+1], b[np*4+2], b[np*4+3], bb + off);
            }
#pragma unroll
            for (int mt = 0; mt < 4; ++mt)
#pragma unroll
                for (int nt = 0; nt < 4; ++nt) {
                    const int bi = (nt >> 1) * 4 + (nt & 1) * 2;
                    mma16816(acc[mt][nt], a[mt], &b[bi]);
                }
        }
        __syncthreads();                         // stage reusable next iter
    }

    // Epilogue: fragment layout -> C.  d0,d1: row lid/4, cols (lid%4)*2,+1;
    // d2,d3: row +8.
    const int er = lid >> 2;
    const int ec = (lid & 3) * 2;
#pragma unroll
    for (int mt = 0; mt < 4; ++mt) {
#pragma unroll
        for (int nt = 0; nt < 4; ++nt) {
            const int r0 = brow + wm + mt * 16 + er;
            const int cc = bcol + wn + nt * 8 + ec;
            *(float2*)&C[(size_t)r0 * FOURH + cc] =
                make_float2(acc[mt][nt][0], acc[mt][nt][1]);
            *(float2*)&C[(size_t)(r0 + 8) * FOURH + cc] =
                make_float2(acc[mt][nt][2], acc[mt][nt][3]);
        }
    }
}

// ---------------------------------------------------------------------------
// Fused LSTM epilogue (validated: rel_err 1.2e-7 on fp32 GEMM inputs):
//   dual LN over 4H, gate math, LN over c1, outputs h1 then c1.
// ---------------------------------------------------------------------------
__device__ __forceinline__ float sigmoidf_(float v) {
    return 1.0f / (1.0f + expf(-v));
}

__global__ __launch_bounds__(256)
void lstm_ln_kernel(const float* __restrict__ c0,
                    const float* __restrict__ bias_x,
                    const float* __restrict__ bias_h,
                    const float* __restrict__ g_ih,
                    const float* __restrict__ b_ih,
                    const float* __restrict__ g_hh,
                    const float* __restrict__ b_hh,
                    const float* __restrict__ g_c,
                    const float* __restrict__ b_c,
                    float* __restrict__ out)
{
    const int b = blockIdx.x;
    const int t = threadIdx.x;
    const int lane = t & 31;
    const int warp = t >> 5;

    const float* wh = g_wh + (size_t)b * FOURH;
    const float* wi = g_wi + (size_t)b * FOURH;

    __shared__ float red[32];

    float vh[8], vi[8];
    float s_h = 0.f, ss_h = 0.f, s_i = 0.f, ss_i = 0.f;
#pragma unroll
    for (int r = 0; r < 8; ++r) {
        const int j = t + 256 * r;
        const float a = wh[j] + bias_h[j];
        const float c = wi[j] + bias_x[j];
        vh[r] = a; vi[r] = c;
        s_h += a; ss_h += a * a;
        s_i += c; ss_i += c * c;
    }
#pragma unroll
    for (int off = 16; off > 0; off >>= 1) {
        s_h  += __shfl_xor_sync(0xffffffffu, s_h,  off);
        ss_h += __shfl_xor_sync(0xffffffffu, ss_h, off);
        s_i  += __shfl_xor_sync(0xffffffffu, s_i,  off);
        ss_i += __shfl_xor_sync(0xffffffffu, ss_i, off);
    }
    if (lane == 0) {
        red[warp]      = s_h;
        red[8 + warp]  = ss_h;
        red[16 + warp] = s_i;
        red[24 + warp] = ss_i;
    }
    __syncthreads();
    float S_h = 0.f, SS_h = 0.f, S_i = 0.f, SS_i = 0.f;
#pragma unroll
    for (int w = 0; w < 8; ++w) {
        S_h  += red[w];
        SS_h += red[8 + w];
        S_i  += red[16 + w];
        SS_i += red[24 + w];
    }

    const float inv4h  = 1.0f / (float)FOURH;
    const float mean_h = S_h * inv4h;
    const float var_h  = SS_h * inv4h - mean_h * mean_h;
    const float rstd_h = rsqrtf(var_h + LN_EPS);
    const float mean_i = S_i * inv4h;
    const float var_i  = SS_i * inv4h - mean_i * mean_i;
    const float rstd_i = rsqrtf(var_i + LN_EPS);

    float s[8];
#pragma unroll
    for (int r = 0; r < 8; ++r) {
        const int j = t + 256 * r;
        const float lh = (vh[r] - mean_h) * rstd_h * g_hh[j] + b_hh[j];
        const float li = (vi[r] - mean_i) * rstd_i * g_ih[j] + b_ih[j];
        s[r] = lh + li;
    }

    const int HD = FOURH / 4;
    const float c0_0 = c0[(size_t)b * HD + t];
    const float c0_1 = c0[(size_t)b * HD + 256 + t];

    const float c1_0 = sigmoidf_(s[0]) * c0_0 + sigmoidf_(s[2]) * tanhf(s[6]);
    const float c1_1 = sigmoidf_(s[1]) * c0_1 + sigmoidf_(s[3]) * tanhf(s[7]);

    float sc  = c1_0 + c1_1;
    float ssc = c1_0 * c1_0 + c1_1 * c1_1;
#pragma unroll
    for (int off = 16; off > 0; off >>= 1) {
        sc  += __shfl_xor_sync(0xffffffffu, sc,  off);
        ssc += __shfl_xor_sync(0xffffffffu, ssc, off);
    }
    __syncthreads();
    if (lane == 0) {
        red[warp]     = sc;
        red[8 + warp] = ssc;
    }
    __syncthreads();
    float Sc = 0.f, SSc = 0.f;
#pragma unroll
    for (int w = 0; w < 8; ++w) { Sc += red[w]; SSc += red[8 + w]; }

    const float invh   = 1.0f / (float)HD;
    const float mean_c = Sc * invh;
    const float var_c  = SSc * invh - mean_c * mean_c;
    const float rstd_c = rsqrtf(var_c + LN_EPS);

    const float lc0 = (c1_0 - mean_c) * rstd_c * g_c[t]       + b_c[t];
    const float lc1 = (c1_1 - mean_c) * rstd_c * g_c[256 + t] + b_c[256 + t];

    const float h1_0 = sigmoidf_(s[4]) * tanhf(lc0);
    const float h1_1 = sigmoidf_(s[5]) * tanhf(lc1);

    float* out_h1 = out;
    float* out_c1 = out + (size_t)BATCH * HD;
    out_h1[(size_t)b * HD + t]       = h1_0;
    out_h1[(size_t)b * HD + 256 + t] = h1_1;
    out_c1[(size_t)b * HD + t]       = c1_0;
    out_c1[(size_t)b * HD + 256 + t] = c1_1;
}

// ---------------------------------------------------------------------------
// Launch
// ---------------------------------------------------------------------------
extern "C" void kernel_launch(void* const* d_in, const int* in_sizes, int n_in,
                              void* d_out, int out_size)
{
    const float* x      = (const float*)d_in[0];
    const float* h0     = (const float*)d_in[1];
    const float* c0     = (const float*)d_in[2];
    const float* w_ih   = (const float*)d_in[3];
    const float* w_hh   = (const float*)d_in[4];
    const float* bias_x = (const float*)d_in[5];
    const float* bias_h = (const float*)d_in[6];
    const float* g_ih   = (const float*)d_in[7];
    const float* b_ih   = (const float*)d_in[8];
    const float* g_hh   = (const float*)d_in[9];
    const float* b_hh   = (const float*)d_in[10];
    const float* g_c    = (const float*)d_in[11];
    const float* b_c    = (const float*)d_in[12];
    float* out = (float*)d_out;

    float *wi_ptr, *wh_ptr;
    __half *x16, *h16, *wih16, *whh16;
    cudaGetSymbolAddress((void**)&wi_ptr, g_wi);
    cudaGetSymbolAddress((void**)&wh_ptr, g_wh);
    cudaGetSymbolAddress((void**)&x16,   g_x16);
    cudaGetSymbolAddress((void**)&h16,   g_h16);
    cudaGetSymbolAddress((void**)&wih16, g_wih16);
    cudaGetSymbolAddress((void**)&whh16, g_whh16);

    cudaFuncSetAttribute(gemm_f16_kernel,
                         cudaFuncAttributeMaxDynamicSharedMemorySize, SMEM_DYN);

    // Activation fp16 conversions
    const size_t n4 = (size_t)BATCH * KDIM / 4;
    cvt16_kernel<<<(unsigned)((n4 + 255) / 256), 256>>>(x,  x16, n4);
    cvt16_kernel<<<(unsigned)((n4 + 255) / 256), 256>>>(h0, h16, n4);

    // Weight transpose + fp16 convert to K-major [4H, K]
    dim3 tb(32, 8);
    dim3 tg(FOURH / 32, KDIM / 32);
    transpose16_kernel<<<tg, tb>>>(w_ih, wih16);
    transpose16_kernel<<<tg, tb>>>(w_hh, whh16);

    // Both GEMMs in one launch: z=0 -> wi (x @ w_ih), z=1 -> wh (h0 @ w_hh)
    dim3 gg(FOURH / BN, BATCH / BM, 2);     // (16, 128, 2)
    gemm_f16_kernel<<<gg, 256, SMEM_DYN>>>(x16, h16, wih16, whh16,
                                           wi_ptr, wh_ptr);

    lstm_ln_kernel<<<BATCH, 256>>>(c0, bias_x, bias_h, g_ih, b_ih,
                                   g_hh, b_hh, g_c, b_c, out);
}

// round 12
// speedup vs baseline: 5.8456x; 1.0219x over previous
#include <cuda_runtime.h>
#include <cuda_fp16.h>
#include <cstdint>
#include <math.h>

// ---------------------------------------------------------------------------
// Problem constants
// ---------------------------------------------------------------------------
#define BATCH   16384
#define KDIM    512          // I == H == 512 (GEMM K)
#define FOURH   2048
#define LN_EPS  1e-5f

// Scratch (device globals: allocation-guard-safe)
// Pre-activations now stored fp16 (halves GEMM-write + epilogue-read traffic)
__device__ __half g_wi[(size_t)BATCH * FOURH];    // x  @ w_ih
__device__ __half g_wh[(size_t)BATCH * FOURH];    // h0 @ w_hh
// fp16 activations (row-major [B, K])
__device__ __half g_x16[(size_t)BATCH * KDIM];
__device__ __half g_h16[(size_t)BATCH * KDIM];
// fp16 transposed weights (K-major [4H, K])
__device__ __half g_wih16[(size_t)FOURH * KDIM];
__device__ __half g_whh16[(size_t)FOURH * KDIM];

// ---------------------------------------------------------------------------
// fp32 -> fp16 convert, 4 elems/thread
// ---------------------------------------------------------------------------
__global__ void cvt16_kernel(const float* __restrict__ src,
                             __half* __restrict__ dst, size_t n4)
{
    const size_t i = (size_t)blockIdx.x * blockDim.x + threadIdx.x;
    if (i >= n4) return;
    const float4 v = ((const float4*)src)[i];
    ((__half2*)dst)[i * 2]     = __floats2half2_rn(v.x, v.y);
    ((__half2*)dst)[i * 2 + 1] = __floats2half2_rn(v.z, v.w);
}

// ---------------------------------------------------------------------------
// Weight transpose+convert: W[K, 4H] fp32 -> WT[4H, K] fp16
// ---------------------------------------------------------------------------
__global__ void transpose16_kernel(const float* __restrict__ W,
                                   __half* __restrict__ WT)
{
    __shared__ float t[32][33];
    const int bx = blockIdx.x * 32;   // col in W  (n)
    const int by = blockIdx.y * 32;   // row in W  (k)
    const int tx = threadIdx.x, ty = threadIdx.y;
#pragma unroll
    for (int i = 0; i < 32; i += 8)
        t[ty + i][tx] = W[(size_t)(by + ty + i) * FOURH + bx + tx];
    __syncthreads();
#pragma unroll
    for (int i = 0; i < 32; i += 8)
        WT[(size_t)(bx + ty + i) * KDIM + by + tx] = __float2half_rn(t[tx][ty + i]);
}

// ---------------------------------------------------------------------------
// mma.sync fp16 GEMM (single-pass, f32 accumulate, fp16 output):
//   C[M,N] = A[M,K] * B[N,K]^T
// CTA tile 128x128, BK=64 (128B rows, xor swizzle), 3-stage cp.async ring
// (96 KB -> 2 CTAs/SM), 8 warps with 64x32 warp tiles of m16n8k16.
// ---------------------------------------------------------------------------
#define BM      128
#define BN      128
#define BKE     64                       // fp16 K-elems per chunk (128 B/row)
#define STAGES  3
#define NKIT    (KDIM / BKE)             // 8
#define TILE_B  (128 * 128)              // 16 KB per operand tile
#define A_OFF   0
#define B_OFF   (TILE_B)
#define STAGE_BYTES (2 * TILE_B)         // 32 KB
#define SMEM_DYN (STAGES * STAGE_BYTES + 1024)   // ~97 KB -> 2 CTAs/SM

__device__ __forceinline__ uint32_t cvta_smem(const void* p) {
    return (uint32_t)__cvta_generic_to_shared(p);
}
__device__ __forceinline__ void cp16(uint32_t dst, const void* src) {
    asm volatile("cp.async.cg.shared.global [%0], [%1], 16;" :: "r"(dst), "l"(src));
}
__device__ __forceinline__ void cp_commit() {
    asm volatile("cp.async.commit_group;" ::: "memory");
}
template <int N>
__device__ __forceinline__ void cp_wait() {
    asm volatile("cp.async.wait_group %0;" :: "n"(N) : "memory");
}
__device__ __forceinline__ void ldsm4(uint32_t& r0, uint32_t& r1,
                                      uint32_t& r2, uint32_t& r3, uint32_t addr) {
    asm volatile("ldmatrix.sync.aligned.m8n8.x4.shared.b16 {%0,%1,%2,%3}, [%4];"
                 : "=r"(r0), "=r"(r1), "=r"(r2), "=r"(r3) : "r"(addr));
}
__device__ __forceinline__ void mma16816(float* d, const uint32_t* a,
                                         const uint32_t* b) {
    asm volatile(
        "mma.sync.aligned.m16n8k16.row.col.f32.f16.f16.f32 "
        "{%0,%1,%2,%3}, {%4,%5,%6,%7}, {%8,%9}, {%0,%1,%2,%3};"
        : "+f"(d[0]), "+f"(d[1]), "+f"(d[2]), "+f"(d[3])
        : "r"(a[0]), "r"(a[1]), "r"(a[2]), "r"(a[3]), "r"(b[0]), "r"(b[1]));
}

__global__ void __launch_bounds__(256, 2)
gemm_f16_kernel(const __half* __restrict__ A0, const __half* __restrict__ A1,
                const __half* __restrict__ B0, const __half* __restrict__ B1,
                __half* __restrict__ C0, __half* __restrict__ C1)
{
    extern __shared__ char dsmem_raw[];

    const int tid = threadIdx.x;
    const int wid = tid >> 5;
    const int lid = tid & 31;

    const __half* A = blockIdx.z ? A1 : A0;
    const __half* B = blockIdx.z ? B1 : B0;
    __half*       C = blockIdx.z ? C1 : C0;

    const int brow = blockIdx.y * BM;
    const int bcol = blockIdx.x * BN;

    uint32_t sbase = cvta_smem(dsmem_raw);
    sbase = (sbase + 127u) & ~127u;

    // Warp tile: 64 (M) x 32 (N);  warp grid 2 x 4
    const int wm = (wid & 1) * 64;
    const int wn = (wid >> 1) * 32;

    // ldmatrix lane->address decode (quad q = lid/8, r = lid%8)
    const int lq = lid >> 3;
    const int lr = lid & 7;
    // A x4: matrices (m0-7,k0-7),(m8-15,k0-7),(m0-7,k8-15),(m8-15,k8-15)
    const int a_row = lr + ((lq & 1) ? 8 : 0);
    const int a_kbh = lq >> 1;               // 0 or 1 -> +16B
    // B x4 over 2 n-tiles: (n0-7,k0-7),(n0-7,k8-15),(n8-15,k0-7),(n8-15,k8-15)
    const int b_row = lr + ((lq >> 1) ? 8 : 0);
    const int b_kbh = lq & 1;

    float acc[4][4][4];
#pragma unroll
    for (int mt = 0; mt < 4; ++mt)
#pragma unroll
        for (int nt = 0; nt < 4; ++nt)
#pragma unroll
            for (int r = 0; r < 4; ++r) acc[mt][nt][r] = 0.0f;

    // Stage loader: 2 tiles of 128 rows x 128 B; 8 cp16 per thread.
    auto load_stage = [&](int s, int kc) {
        const int k0 = kc * BKE;
        const uint32_t sb = sbase + s * STAGE_BYTES;
#pragma unroll
        for (int i = 0; i < 4; ++i) {
            const int idx = tid + 256 * i;       // 0..1023
            const int row = idx >> 3, ch = idx & 7;
            const uint32_t off = (uint32_t)(row * 128 + ((ch ^ (row & 7)) * 16));
            const size_t ga = (size_t)(brow + row) * KDIM + k0 + ch * 8;
            const size_t gb = (size_t)(bcol + row) * KDIM + k0 + ch * 8;
            cp16(sb + A_OFF + off, A + ga);
            cp16(sb + B_OFF + off, B + gb);
        }
        cp_commit();
    };

    // Prologue: 2 stages in flight
    load_stage(0, 0);
    load_stage(1, 1);

#pragma unroll 1
    for (int kc = 0; kc < NKIT; ++kc) {
        const int s = kc % STAGES;
        if (kc + 2 < NKIT) load_stage((kc + 2) % STAGES, kc + 2);
        else               cp_commit();          // empty group: keeps wait<2> exact
        cp_wait<2>();                            // chunk kc resident
        __syncthreads();

        const uint32_t ab = sbase + s * STAGE_BYTES + A_OFF;
        const uint32_t bb = sbase + s * STAGE_BYTES + B_OFF;

#pragma unroll
        for (int ks = 0; ks < 4; ++ks) {
            uint32_t a[4][4], b[8];
#pragma unroll
            for (int mt = 0; mt < 4; ++mt) {
                const int row = wm + mt * 16 + a_row;
                const int ch  = ks * 2 + a_kbh;
                const uint32_t off =
                    (uint32_t)(row * 128 + ((ch ^ (row & 7)) * 16));
                ldsm4(a[mt][0], a[mt][1], a[mt][2], a[mt][3], ab + off);
            }
#pragma unroll
            for (int np = 0; np < 2; ++np) {
                const int row = wn + np * 16 + b_row;
                const int ch  = ks * 2 + b_kbh;
                const uint32_t off =
                    (uint32_t)(row * 128 + ((ch ^ (row & 7)) * 16));
                ldsm4(b[np*4], b[np*4+1], b[np*4+2], b[np*4+3], bb + off);
            }
#pragma unroll
            for (int mt = 0; mt < 4; ++mt)
#pragma unroll
                for (int nt = 0; nt < 4; ++nt) {
                    const int bi = (nt >> 1) * 4 + (nt & 1) * 2;
                    mma16816(acc[mt][nt], a[mt], &b[bi]);
                }
        }
        __syncthreads();                         // stage reusable next iter
    }

    // Epilogue: fragment layout -> C (fp16).  d0,d1: row lid/4, cols
    // (lid%4)*2,+1;  d2,d3: row +8.  cc is even -> half2 stores aligned.
    const int er = lid >> 2;
    const int ec = (lid & 3) * 2;
#pragma unroll
    for (int mt = 0; mt < 4; ++mt) {
#pragma unroll
        for (int nt = 0; nt < 4; ++nt) {
            const int r0 = brow + wm + mt * 16 + er;
            const int cc = bcol + wn + nt * 8 + ec;
            *(__half2*)&C[(size_t)r0 * FOURH + cc] =
                __floats2half2_rn(acc[mt][nt][0], acc[mt][nt][1]);
            *(__half2*)&C[(size_t)(r0 + 8) * FOURH + cc] =
                __floats2half2_rn(acc[mt][nt][2], acc[mt][nt][3]);
        }
    }
}

// ---------------------------------------------------------------------------
// Fused LSTM epilogue, half2-vectorized:
//   reads fp16 wi/wh as half2 (p = t + 256*r, r = gate index), dual LN over
//   4H, gate math, LN over c1, outputs h1 then c1 (fp32).
// Thread t handles hidden units 2t and 2t+1 of every gate.
// ---------------------------------------------------------------------------
__device__ __forceinline__ float sigmoidf_(float v) {
    return 1.0f / (1.0f + expf(-v));
}

__global__ __launch_bounds__(256)
void lstm_ln_kernel(const float* __restrict__ c0,
                    const float* __restrict__ bias_x,
                    const float* __restrict__ bias_h,
                    const float* __restrict__ g_ih,
                    const float* __restrict__ b_ih,
                    const float* __restrict__ g_hh,
                    const float* __restrict__ b_hh,
                    const float* __restrict__ g_c,
                    const float* __restrict__ b_c,
                    float* __restrict__ out)
{
    const int b = blockIdx.x;
    const int t = threadIdx.x;
    const int lane = t & 31;
    const int warp = t >> 5;

    const __half2* wh2 = (const __half2*)g_wh + (size_t)b * (FOURH / 2);
    const __half2* wi2 = (const __half2*)g_wi + (size_t)b * (FOURH / 2);

    __shared__ float red[32];

    // r indexes the gate (f=0, i=1, o=2, g=3); pair p = t + 256*r covers
    // elements 2p, 2p+1 = gate r, hidden units 2t, 2t+1.
    float2 vh[4], vi[4];
    float s_h = 0.f, ss_h = 0.f, s_i = 0.f, ss_i = 0.f;
#pragma unroll
    for (int r = 0; r < 4; ++r) {
        const int p = t + 256 * r;
        const int j = p * 2;
        float2 a = __half22float2(wh2[p]);
        float2 c = __half22float2(wi2[p]);
        const float2 bh = *(const float2*)&bias_h[j];
        const float2 bx = *(const float2*)&bias_x[j];
        a.x += bh.x; a.y += bh.y;
        c.x += bx.x; c.y += bx.y;
        vh[r] = a; vi[r] = c;
        s_h += a.x + a.y; ss_h += a.x * a.x + a.y * a.y;
        s_i += c.x + c.y; ss_i += c.x * c.x + c.y * c.y;
    }

#pragma unroll
    for (int off = 16; off > 0; off >>= 1) {
        s_h  += __shfl_xor_sync(0xffffffffu, s_h,  off);
        ss_h += __shfl_xor_sync(0xffffffffu, ss_h, off);
        s_i  += __shfl_xor_sync(0xffffffffu, s_i,  off);
        ss_i += __shfl_xor_sync(0xffffffffu, ss_i, off);
    }
    if (lane == 0) {
        red[warp]      = s_h;
        red[8 + warp]  = ss_h;
        red[16 + warp] = s_i;
        red[24 + warp] = ss_i;
    }
    __syncthreads();
    float S_h = 0.f, SS_h = 0.f, S_i = 0.f, SS_i = 0.f;
#pragma unroll
    for (int w = 0; w < 8; ++w) {
        S_h  += red[w];
        SS_h += red[8 + w];
        S_i  += red[16 + w];
        SS_i += red[24 + w];
    }

    const float inv4h  = 1.0f / (float)FOURH;
    const float mean_h = S_h * inv4h;
    const float var_h  = SS_h * inv4h - mean_h * mean_h;
    const float rstd_h = rsqrtf(var_h + LN_EPS);
    const float mean_i = S_i * inv4h;
    const float var_i  = SS_i * inv4h - mean_i * mean_i;
    const float rstd_i = rsqrtf(var_i + LN_EPS);

    float2 s[4];
#pragma unroll
    for (int r = 0; r < 4; ++r) {
        const int j = (t + 256 * r) * 2;
        const float2 gh = *(const float2*)&g_hh[j];
        const float2 bh = *(const float2*)&b_hh[j];
        const float2 gi = *(const float2*)&g_ih[j];
        const float2 bi = *(const float2*)&b_ih[j];
        s[r].x = (vh[r].x - mean_h) * rstd_h * gh.x + bh.x
               + (vi[r].x - mean_i) * rstd_i * gi.x + bi.x;
        s[r].y = (vh[r].y - mean_h) * rstd_h * gh.y + bh.y
               + (vi[r].y - mean_i) * rstd_i * gi.y + bi.y;
    }

    const int HD = FOURH / 4;
    const float2 c0v = *(const float2*)&c0[(size_t)b * HD + 2 * t];

    // s[0]=f, s[1]=i, s[2]=o, s[3]=g  for hidden units 2t (.x), 2t+1 (.y)
    const float c1_0 = sigmoidf_(s[0].x) * c0v.x + sigmoidf_(s[1].x) * tanhf(s[3].x);
    const float c1_1 = sigmoidf_(s[0].y) * c0v.y + sigmoidf_(s[1].y) * tanhf(s[3].y);

    float sc  = c1_0 + c1_1;
    float ssc = c1_0 * c1_0 + c1_1 * c1_1;
#pragma unroll
    for (int off = 16; off > 0; off >>= 1) {
        sc  += __shfl_xor_sync(0xffffffffu, sc,  off);
        ssc += __shfl_xor_sync(0xffffffffu, ssc, off);
    }
    __syncthreads();   // protect red[] reuse
    if (lane == 0) {
        red[warp]     = sc;
        red[8 + warp] = ssc;
    }
    __syncthreads();
    float Sc = 0.f, SSc = 0.f;
#pragma unroll
    for (int w = 0; w < 8; ++w) { Sc += red[w]; SSc += red[8 + w]; }

    const float invh   = 1.0f / (float)HD;
    const float mean_c = Sc * invh;
    const float var_c  = SSc * invh - mean_c * mean_c;
    const float rstd_c = rsqrtf(var_c + LN_EPS);

    const float2 gc = *(const float2*)&g_c[2 * t];
    const float2 bc = *(const float2*)&b_c[2 * t];
    const float lc0 = (c1_0 - mean_c) * rstd_c * gc.x + bc.x;
    const float lc1 = (c1_1 - mean_c) * rstd_c * gc.y + bc.y;

    const float h1_0 = sigmoidf_(s[2].x) * tanhf(lc0);
    const float h1_1 = sigmoidf_(s[2].y) * tanhf(lc1);

    float* out_h1 = out;
    float* out_c1 = out + (size_t)BATCH * HD;
    *(float2*)&out_h1[(size_t)b * HD + 2 * t] = make_float2(h1_0, h1_1);
    *(float2*)&out_c1[(size_t)b * HD + 2 * t] = make_float2(c1_0, c1_1);
}

// ---------------------------------------------------------------------------
// Launch
// ---------------------------------------------------------------------------
extern "C" void kernel_launch(void* const* d_in, const int* in_sizes, int n_in,
                              void* d_out, int out_size)
{
    const float* x      = (const float*)d_in[0];
    const float* h0     = (const float*)d_in[1];
    const float* c0     = (const float*)d_in[2];
    const float* w_ih   = (const float*)d_in[3];
    const float* w_hh   = (const float*)d_in[4];
    const float* bias_x = (const float*)d_in[5];
    const float* bias_h = (const float*)d_in[6];
    const float* g_ih   = (const float*)d_in[7];
    const float* b_ih   = (const float*)d_in[8];
    const float* g_hh   = (const float*)d_in[9];
    const float* b_hh   = (const float*)d_in[10];
    const float* g_c    = (const float*)d_in[11];
    const float* b_c    = (const float*)d_in[12];
    float* out = (float*)d_out;

    __half *wi_ptr, *wh_ptr, *x16, *h16, *wih16, *whh16;
    cudaGetSymbolAddress((void**)&wi_ptr, g_wi);
    cudaGetSymbolAddress((void**)&wh_ptr, g_wh);
    cudaGetSymbolAddress((void**)&x16,   g_x16);
    cudaGetSymbolAddress((void**)&h16,   g_h16);
    cudaGetSymbolAddress((void**)&wih16, g_wih16);
    cudaGetSymbolAddress((void**)&whh16, g_whh16);

    cudaFuncSetAttribute(gemm_f16_kernel,
                         cudaFuncAttributeMaxDynamicSharedMemorySize, SMEM_DYN);

    // Activation fp16 conversions
    const size_t n4 = (size_t)BATCH * KDIM / 4;
    cvt16_kernel<<<(unsigned)((n4 + 255) / 256), 256>>>(x,  x16, n4);
    cvt16_kernel<<<(unsigned)((n4 + 255) / 256), 256>>>(h0, h16, n4);

    // Weight transpose + fp16 convert to K-major [4H, K]
    dim3 tb(32, 8);
    dim3 tg(FOURH / 32, KDIM / 32);
    transpose16_kernel<<<tg, tb>>>(w_ih, wih16);
    transpose16_kernel<<<tg, tb>>>(w_hh, whh16);

    // Both GEMMs in one launch: z=0 -> wi (x @ w_ih), z=1 -> wh (h0 @ w_hh)
    dim3 gg(FOURH / BN, BATCH / BM, 2);     // (16, 128, 2)
    gemm_f16_kernel<<<gg, 256, SMEM_DYN>>>(x16, h16, wih16, whh16,
                                           wi_ptr, wh_ptr);

    lstm_ln_kernel<<<BATCH, 256>>>(c0, bias_x, bias_h, g_ih, b_ih,
                                   g_hh, b_hh, g_c, b_c, out);
}